// round 15
// baseline (speedup 1.0000x reference)
#include <cuda_runtime.h>
#include <cuda_bf16.h>
#include <cstddef>

#define B_  2
#define T_  2048
#define C_  2048
#define H_  16
#define HK_ 4
#define HD_ 128
#define BT_ (B_*T_)

// fp32 intermediates
__device__ float g_qt[(size_t)BT_ * 2048];
__device__ float g_kt[(size_t)BT_ * 512];
__device__ float g_vt[(size_t)BT_ * 512];
// packed bf16 hi/lo operands
__device__ unsigned g_xph[(size_t)BT_ * 1024], g_xpl[(size_t)BT_ * 1024];
__device__ unsigned g_yph[(size_t)BT_ * 1024], g_ypl[(size_t)BT_ * 1024];
__device__ unsigned g_wqph[(size_t)1024 * 2048], g_wqpl[(size_t)1024 * 2048];
__device__ unsigned g_wkph[(size_t)1024 * 512],  g_wkpl[(size_t)1024 * 512];
__device__ unsigned g_wvph[(size_t)1024 * 512],  g_wvpl[(size_t)1024 * 512];
__device__ unsigned g_woph[(size_t)1024 * 2048], g_wopl[(size_t)1024 * 2048];
__device__ unsigned g_qph[(size_t)B_*H_ *T_*64], g_qpl[(size_t)B_*H_ *T_*64];
__device__ unsigned g_kph[(size_t)B_*HK_*64*T_], g_kpl[(size_t)B_*HK_*64*T_];
__device__ unsigned g_vph[(size_t)B_*HK_*(T_/2)*128], g_vpl[(size_t)B_*HK_*(T_/2)*128];

#define MMA_BF16(Cacc, Af, b0, b1)                                                 \
    asm volatile("mma.sync.aligned.m16n8k16.row.col.f32.bf16.bf16.f32 "            \
        "{%0,%1,%2,%3}, {%4,%5,%6,%7}, {%8,%9}, {%0,%1,%2,%3};"                    \
        : "+f"(Cacc[0]), "+f"(Cacc[1]), "+f"(Cacc[2]), "+f"(Cacc[3])               \
        : "r"(Af[0]), "r"(Af[1]), "r"(Af[2]), "r"(Af[3]), "r"(b0), "r"(b1))

__device__ __forceinline__ void split2(float a, float b, unsigned& h, unsigned& l) {
    __nv_bfloat162 hb = __floats2bfloat162_rn(a, b);
    float ha = __bfloat162float(hb.x), hbv = __bfloat162float(hb.y);
    __nv_bfloat162 lb = __floats2bfloat162_rn(a - ha, b - hbv);
    h = *reinterpret_cast<unsigned*>(&hb);
    l = *reinterpret_cast<unsigned*>(&lb);
}

// ---------------- prep kernels ----------------
__global__ void split_pack_rows(const float* __restrict__ in, unsigned* __restrict__ oh,
                                unsigned* __restrict__ ol, int n8) {
    int i = blockIdx.x * blockDim.x + threadIdx.x;
    if (i >= n8) return;
    float4 a = ((const float4*)in)[2*i], b = ((const float4*)in)[2*i + 1];
    uint4 h, l;
    split2(a.x, a.y, h.x, l.x);  split2(a.z, a.w, h.y, l.y);
    split2(b.x, b.y, h.z, l.z);  split2(b.z, b.w, h.w, l.w);
    ((uint4*)oh)[i] = h;  ((uint4*)ol)[i] = l;
}

__global__ void pack_w(const float* __restrict__ W, unsigned* __restrict__ oh,
                       unsigned* __restrict__ ol, int K, int N) {
    int i = blockIdx.x * blockDim.x + threadIdx.x;
    int n4q = N >> 2;
    if (i >= (K/2) * n4q) return;
    int kp = i / n4q, n4 = (i % n4q) * 4;
    float4 r0 = *(const float4*)(W + (size_t)(2*kp)     * N + n4);
    float4 r1 = *(const float4*)(W + (size_t)(2*kp + 1) * N + n4);
    uint4 h, l;
    split2(r0.x, r1.x, h.x, l.x);  split2(r0.y, r1.y, h.y, l.y);
    split2(r0.z, r1.z, h.z, l.z);  split2(r0.w, r1.w, h.w, l.w);
    *(uint4*)(oh + (size_t)kp * N + n4) = h;
    *(uint4*)(ol + (size_t)kp * N + n4) = l;
}

// ---------------- 3xBF16 GEMM, double-buffered, BK=32 elems (16 pairs) ----------------
// dynamic smem, per buffer (u32): Ah[128][20] @0, Al @2560, Wh[16][136] @5120, Wl @7296
#define GB_AH 0
#define GB_AL 2560
#define GB_WH 5120
#define GB_WL 7296
#define GB_STRIDE 9472
#define GB_BYTES (2 * GB_STRIDE * 4)

__global__ __launch_bounds__(256) void gemm_pk_kernel(
    const unsigned* __restrict__ Aph, const unsigned* __restrict__ Apl,
    const unsigned* __restrict__ Wph, const unsigned* __restrict__ Wpl,
    const float* __restrict__ bias, float* __restrict__ Cout,
    int M, int N, int Kp)
{
    extern __shared__ unsigned sg[];
    const int tid  = threadIdx.x;
    const int bm   = blockIdx.y * 128, bn = blockIdx.x * 128;
    const int lane = tid & 31, warp = tid >> 5;
    const int wm   = (warp & 3) * 32, wn = (warp >> 2) * 64;
    const int g    = lane >> 2, tg = lane & 3;

    const int arow = tid >> 1, ahalf = (tid & 1) * 8;   // A: 8 u32 per thread
    const int wkp  = tid >> 4, wn8   = (tid & 15) * 8;  // W: 8 u32 per thread

    uint4 aH0, aH1, aL0, aL1, wH0, wH1, wL0, wL1;
    float c[2][8][4];
#pragma unroll
    for (int mt = 0; mt < 2; mt++)
#pragma unroll
        for (int nt = 0; nt < 8; nt++)
#pragma unroll
            for (int i = 0; i < 4; i++) c[mt][nt][i] = 0.f;

    auto loadG = [&](int kp0) {
        const unsigned* pa = Aph + (size_t)(bm + arow) * Kp + kp0 + ahalf;
        const unsigned* pl = Apl + (size_t)(bm + arow) * Kp + kp0 + ahalf;
        aH0 = *(const uint4*)pa;  aH1 = *(const uint4*)(pa + 4);
        aL0 = *(const uint4*)pl;  aL1 = *(const uint4*)(pl + 4);
        const unsigned* pw = Wph + (size_t)(kp0 + wkp) * N + bn + wn8;
        const unsigned* pq = Wpl + (size_t)(kp0 + wkp) * N + bn + wn8;
        wH0 = *(const uint4*)pw;  wH1 = *(const uint4*)(pw + 4);
        wL0 = *(const uint4*)pq;  wL1 = *(const uint4*)(pq + 4);
    };
    auto storeS = [&](unsigned* buf) {
        *(uint4*)&buf[GB_AH + arow * 20 + ahalf]     = aH0;
        *(uint4*)&buf[GB_AH + arow * 20 + ahalf + 4] = aH1;
        *(uint4*)&buf[GB_AL + arow * 20 + ahalf]     = aL0;
        *(uint4*)&buf[GB_AL + arow * 20 + ahalf + 4] = aL1;
        *(uint4*)&buf[GB_WH + wkp * 136 + wn8]     = wH0;
        *(uint4*)&buf[GB_WH + wkp * 136 + wn8 + 4] = wH1;
        *(uint4*)&buf[GB_WL + wkp * 136 + wn8]     = wL0;
        *(uint4*)&buf[GB_WL + wkp * 136 + wn8 + 4] = wL1;
    };
    auto computeTile = [&](const unsigned* buf) {
#pragma unroll
        for (int ks = 0; ks < 2; ks++) {
            const int kb = ks * 8;
            unsigned ah[2][4], al[2][4];
#pragma unroll
            for (int mt = 0; mt < 2; mt++) {
                int r = wm + mt * 16;
                ah[mt][0] = buf[GB_AH + (r + g    ) * 20 + kb + tg    ];
                ah[mt][1] = buf[GB_AH + (r + g + 8) * 20 + kb + tg    ];
                ah[mt][2] = buf[GB_AH + (r + g    ) * 20 + kb + tg + 4];
                ah[mt][3] = buf[GB_AH + (r + g + 8) * 20 + kb + tg + 4];
                al[mt][0] = buf[GB_AL + (r + g    ) * 20 + kb + tg    ];
                al[mt][1] = buf[GB_AL + (r + g + 8) * 20 + kb + tg    ];
                al[mt][2] = buf[GB_AL + (r + g    ) * 20 + kb + tg + 4];
                al[mt][3] = buf[GB_AL + (r + g + 8) * 20 + kb + tg + 4];
            }
#pragma unroll
            for (int nt = 0; nt < 8; nt++) {
                int cn = wn + nt * 8 + g;
                unsigned bh0 = buf[GB_WH + (kb + tg    ) * 136 + cn];
                unsigned bh1 = buf[GB_WH + (kb + tg + 4) * 136 + cn];
                unsigned bl0 = buf[GB_WL + (kb + tg    ) * 136 + cn];
                unsigned bl1 = buf[GB_WL + (kb + tg + 4) * 136 + cn];
#pragma unroll
                for (int mt = 0; mt < 2; mt++) {
                    MMA_BF16(c[mt][nt], ah[mt], bh0, bh1);
                    MMA_BF16(c[mt][nt], al[mt], bh0, bh1);
                    MMA_BF16(c[mt][nt], ah[mt], bl0, bl1);
                }
            }
        }
    };

    const int ntiles = Kp >> 4;   // BK = 16 pairs
    loadG(0);
    storeS(sg);
    __syncthreads();
    for (int t = 1; t < ntiles; t++) {
        loadG(t << 4);
        computeTile(sg + ((t - 1) & 1) * GB_STRIDE);
        storeS(sg + (t & 1) * GB_STRIDE);
        __syncthreads();
    }
    computeTile(sg + ((ntiles - 1) & 1) * GB_STRIDE);

#pragma unroll
    for (int mt = 0; mt < 2; mt++) {
        int r0 = bm + wm + mt * 16 + g;
#pragma unroll
        for (int nt = 0; nt < 8; nt++) {
            int col = bn + wn + nt * 8 + tg * 2;
            float b0 = 0.f, b1 = 0.f;
            if (bias) { b0 = bias[col]; b1 = bias[col + 1]; }
            float2 v0 = {c[mt][nt][0] + b0, c[mt][nt][1] + b1};
            float2 v1 = {c[mt][nt][2] + b0, c[mt][nt][3] + b1};
            *(float2*)(Cout + (size_t)r0 * N + col)       = v0;
            *(float2*)(Cout + (size_t)(r0 + 8) * N + col) = v1;
        }
    }
}

// ---------------- RoPE + pack Q ----------------
__global__ void rope_pack_kernel(const float* __restrict__ in, const float* __restrict__ cosp,
                                 const float* __restrict__ sinp, unsigned* __restrict__ oh,
                                 unsigned* __restrict__ ol, int Hn) {
    int idx = blockIdx.x * blockDim.x + threadIdx.x;
    int total = B_ * T_ * Hn * 32;
    if (idx >= total) return;
    int d2 = idx & 31;
    int h  = (idx >> 5) % Hn;
    int t  = (idx >> 5) / Hn % T_;
    int b  = (idx >> 5) / Hn / T_;
    size_t ib = ((size_t)(b * T_ + t) * Hn + h) * HD_ + 2 * d2;
    float2 x01 = *(const float2*)(in + ib);
    float2 x23 = *(const float2*)(in + ib + 64);
    size_t cb = (size_t)(b * T_ + t) * HD_ + 2 * d2;
    float2 c01 = *(const float2*)(cosp + cb), c23 = *(const float2*)(cosp + cb + 64);
    float2 s01 = *(const float2*)(sinp + cb), s23 = *(const float2*)(sinp + cb + 64);
    float o0 = x01.x * c01.x - x23.x * s01.x;
    float o1 = x01.y * c01.y - x23.y * s01.y;
    float o2 = x23.x * c23.x + x01.x * s23.x;
    float o3 = x23.y * c23.y + x01.y * s23.y;
    size_t ob = ((size_t)(b * Hn + h) * T_ + t) * 64 + d2;
    unsigned hA, lA, hB, lB;
    split2(o0, o1, hA, lA);
    split2(o2, o3, hB, lB);
    oh[ob] = hA;  ol[ob] = lA;
    oh[ob + 32] = hB;  ol[ob + 32] = lB;
}

// ---------------- RoPE + pack K transposed: -> [B,HK,64pair,T] ----------------
__global__ void rope_pack_kt_kernel(const float* __restrict__ in, const float* __restrict__ cosp,
                                    const float* __restrict__ sinp, unsigned* __restrict__ oh,
                                    unsigned* __restrict__ ol) {
    int idx = blockIdx.x * blockDim.x + threadIdx.x;
    int total = B_ * T_ * HK_ * 32;
    if (idx >= total) return;
    int d2 = idx & 31;
    int h  = (idx >> 5) % HK_;
    int t  = (idx >> 5) / HK_ % T_;
    int b  = (idx >> 5) / HK_ / T_;
    size_t ib = ((size_t)(b * T_ + t) * HK_ + h) * HD_ + 2 * d2;
    float2 x01 = *(const float2*)(in + ib);
    float2 x23 = *(const float2*)(in + ib + 64);
    size_t cb = (size_t)(b * T_ + t) * HD_ + 2 * d2;
    float2 c01 = *(const float2*)(cosp + cb), c23 = *(const float2*)(cosp + cb + 64);
    float2 s01 = *(const float2*)(sinp + cb), s23 = *(const float2*)(sinp + cb + 64);
    float o0 = x01.x * c01.x - x23.x * s01.x;
    float o1 = x01.y * c01.y - x23.y * s01.y;
    float o2 = x23.x * c23.x + x01.x * s23.x;
    float o3 = x23.y * c23.y + x01.y * s23.y;
    unsigned hA, lA, hB, lB;
    split2(o0, o1, hA, lA);
    split2(o2, o3, hB, lB);
    size_t ob = ((size_t)(b * HK_ + h) * 64 + d2) * T_ + t;
    oh[ob] = hA;  ol[ob] = lA;
    oh[ob + (size_t)32 * T_] = hB;  ol[ob + (size_t)32 * T_] = lB;
}

// ---------------- pack V ----------------
__global__ void pack_v_kernel(const float* __restrict__ in, unsigned* __restrict__ oh,
                              unsigned* __restrict__ ol) {
    int idx = blockIdx.x * blockDim.x + threadIdx.x;
    int total = B_ * HK_ * (T_/2) * 32;
    if (idx >= total) return;
    int d4 = (idx & 31) * 4;
    int tp = (idx >> 5) % (T_/2);
    int hk = (idx >> 5) / (T_/2) % HK_;
    int b  = (idx >> 5) / (T_/2) / HK_;
    float4 r0 = *(const float4*)(in + ((size_t)(b * T_ + 2*tp)     * HK_ + hk) * HD_ + d4);
    float4 r1 = *(const float4*)(in + ((size_t)(b * T_ + 2*tp + 1) * HK_ + hk) * HD_ + d4);
    uint4 h, l;
    split2(r0.x, r1.x, h.x, l.x);  split2(r0.y, r1.y, h.y, l.y);
    split2(r0.z, r1.z, h.z, l.z);  split2(r0.w, r1.w, h.w, l.w);
    size_t ob = ((size_t)(b * HK_ + hk) * (T_/2) + tp) * 128 + d4;
    *(uint4*)(oh + ob) = h;
    *(uint4*)(ol + ob) = l;
}

// ---------------- flash attention: 128-row Q tiles, packed output ----------------
#define AT_QH 0
#define AT_QL (AT_QH + 128*68)
#define AT_KH (AT_QL + 128*68)
#define AT_KL (AT_KH + 64*68)
#define AT_VH (AT_KL + 64*68)
#define AT_VL (AT_VH + 32*132)
#define AT_SS (AT_VL + 32*132)
#define AT_PH (AT_SS + 128*68)
#define AT_PL (AT_PH + 128*36)
#define AT_RM (AT_PL + 128*36)
#define AT_U32 (AT_RM + 384)
#define AT_BYTES (AT_U32 * 4)

__global__ __launch_bounds__(256) void attn_pk_kernel(
    const unsigned* __restrict__ qh, const unsigned* __restrict__ ql,
    const unsigned* __restrict__ kh, const unsigned* __restrict__ kl,
    const unsigned* __restrict__ vh, const unsigned* __restrict__ vl,
    unsigned* __restrict__ yph, unsigned* __restrict__ ypl)
{
    extern __shared__ unsigned su[];
    unsigned* Qh = su + AT_QH;  unsigned* Ql = su + AT_QL;
    unsigned* Kh = su + AT_KH;  unsigned* Kl = su + AT_KL;
    unsigned* Vh = su + AT_VH;  unsigned* Vl = su + AT_VL;
    float*    Ss = (float*)(su + AT_SS);
    unsigned* Ph = su + AT_PH;  unsigned* Pl = su + AT_PL;
    float*  rowm = (float*)(su + AT_RM);
    float*  rowl = rowm + 128;
    float* rowsc = rowl + 128;

    const int qt = (gridDim.x - 1) - blockIdx.x;
    const int h = blockIdx.y, b = blockIdx.z;
    const int grp = h >> 2;
    const int tid = threadIdx.x, lane = tid & 31, warp = tid >> 5;
    const int gg = lane >> 2, tg = lane & 3;
    const int wm = warp * 16;
    const float SC = 0.08838834764831845f;

    const unsigned* qbh = qh + (((size_t)b * H_ + h) * T_ + (size_t)qt * 128) * 64;
    const unsigned* qbl = ql + (((size_t)b * H_ + h) * T_ + (size_t)qt * 128) * 64;
    const unsigned* kbh = kh + ((size_t)b * HK_ + grp) * 64 * T_;
    const unsigned* kbl = kl + ((size_t)b * HK_ + grp) * 64 * T_;
    const unsigned* vbh = vh + ((size_t)b * HK_ + grp) * (T_/2) * 128;
    const unsigned* vbl = vl + ((size_t)b * HK_ + grp) * (T_/2) * 128;

#pragma unroll
    for (int p = 0; p < 8; p++) {
        int idx = tid + p * 256;
        int row = idx >> 4, c4 = (idx & 15) * 4;
        *(uint4*)&Qh[row * 68 + c4] = *(const uint4*)(qbh + (size_t)row * 64 + c4);
        *(uint4*)&Ql[row * 68 + c4] = *(const uint4*)(qbl + (size_t)row * 64 + c4);
    }
    if (tid < 128) { rowm[tid] = -1e30f; rowl[tid] = 0.f; }

    float c2[16][4];
#pragma unroll
    for (int nt = 0; nt < 16; nt++)
#pragma unroll
        for (int i = 0; i < 4; i++) c2[nt][i] = 0.f;

    const int nkt = 2 * qt + 2;
    for (int kt = 0; kt < nkt; kt++) {
        __syncthreads();
#pragma unroll
        for (int p = 0; p < 4; p++) {
            int idx = tid + p * 256;
            int pr = idx >> 4, c4 = (idx & 15) * 4;
            *(uint4*)&Kh[pr * 68 + c4] = *(const uint4*)(kbh + (size_t)pr * T_ + kt * 64 + c4);
            *(uint4*)&Kl[pr * 68 + c4] = *(const uint4*)(kbl + (size_t)pr * T_ + kt * 64 + c4);
        }
#pragma unroll
        for (int p = 0; p < 4; p++) {
            int idx = tid + p * 256;
            int row = idx >> 5, c4 = (idx & 31) * 4;
            *(uint4*)&Vh[row * 132 + c4] = *(const uint4*)(vbh + ((size_t)kt * 32 + row) * 128 + c4);
            *(uint4*)&Vl[row * 132 + c4] = *(const uint4*)(vbl + ((size_t)kt * 32 + row) * 128 + c4);
        }
        __syncthreads();

        float cs[8][4];
#pragma unroll
        for (int nt = 0; nt < 8; nt++)
#pragma unroll
            for (int i = 0; i < 4; i++) cs[nt][i] = 0.f;

#pragma unroll
        for (int kp8 = 0; kp8 < 64; kp8 += 8) {
            unsigned ah[4], al[4];
            ah[0] = Qh[(wm + gg    ) * 68 + kp8 + tg    ];
            ah[1] = Qh[(wm + gg + 8) * 68 + kp8 + tg    ];
            ah[2] = Qh[(wm + gg    ) * 68 + kp8 + tg + 4];
            ah[3] = Qh[(wm + gg + 8) * 68 + kp8 + tg + 4];
            al[0] = Ql[(wm + gg    ) * 68 + kp8 + tg    ];
            al[1] = Ql[(wm + gg + 8) * 68 + kp8 + tg    ];
            al[2] = Ql[(wm + gg    ) * 68 + kp8 + tg + 4];
            al[3] = Ql[(wm + gg + 8) * 68 + kp8 + tg + 4];
#pragma unroll
            for (int nt = 0; nt < 8; nt++) {
                int cn = nt * 8 + gg;
                unsigned bh0 = Kh[(kp8 + tg    ) * 68 + cn];
                unsigned bh1 = Kh[(kp8 + tg + 4) * 68 + cn];
                unsigned bl0 = Kl[(kp8 + tg    ) * 68 + cn];
                unsigned bl1 = Kl[(kp8 + tg + 4) * 68 + cn];
                MMA_BF16(cs[nt], ah, bh0, bh1);
                MMA_BF16(cs[nt], al, bh0, bh1);
                MMA_BF16(cs[nt], ah, bl0, bl1);
            }
        }
        {
            int qi0 = qt * 128 + wm + gg;
            int qi1 = qi0 + 8;
#pragma unroll
            for (int nt = 0; nt < 8; nt++) {
                int col = nt * 8 + tg * 2;
                int kj = kt * 64 + col;
                Ss[(wm + gg    ) * 68 + col    ] = (kj     <= qi0) ? cs[nt][0] * SC : -1e30f;
                Ss[(wm + gg    ) * 68 + col + 1] = (kj + 1 <= qi0) ? cs[nt][1] * SC : -1e30f;
                Ss[(wm + gg + 8) * 68 + col    ] = (kj     <= qi1) ? cs[nt][2] * SC : -1e30f;
                Ss[(wm + gg + 8) * 68 + col + 1] = (kj + 1 <= qi1) ? cs[nt][3] * SC : -1e30f;
            }
        }
        __syncthreads();

        {
            int r = tid >> 1, part = tid & 1, base = part * 32;
            float mold = rowm[r];
            float tmax = mold;
            float pv[32];
#pragma unroll
            for (int j = 0; j < 32; j++) { pv[j] = Ss[r * 68 + base + j]; tmax = fmaxf(tmax, pv[j]); }
            tmax = fmaxf(tmax, __shfl_xor_sync(0xFFFFFFFFu, tmax, 1));
            float sum = 0.f;
#pragma unroll
            for (int j = 0; j < 32; j++) { pv[j] = __expf(pv[j] - tmax); sum += pv[j]; }
            sum += __shfl_xor_sync(0xFFFFFFFFu, sum, 1);
#pragma unroll
            for (int j = 0; j < 16; j++) {
                unsigned hh, ll;
                split2(pv[2*j], pv[2*j + 1], hh, ll);
                Ph[r * 36 + part * 16 + j] = hh;
                Pl[r * 36 + part * 16 + j] = ll;
            }
            if (part == 0) {
                float sc = __expf(mold - tmax);
                rowsc[r] = sc;
                rowl[r] = rowl[r] * sc + sum;
                rowm[r] = tmax;
            }
        }
        __syncthreads();

        {
            float s0 = rowsc[wm + gg], s1 = rowsc[wm + gg + 8];
#pragma unroll
            for (int nt = 0; nt < 16; nt++) {
                c2[nt][0] *= s0; c2[nt][1] *= s0;
                c2[nt][2] *= s1; c2[nt][3] *= s1;
            }
        }
#pragma unroll
        for (int kp8 = 0; kp8 < 32; kp8 += 8) {
            unsigned ah[4], al[4];
            ah[0] = Ph[(wm + gg    ) * 36 + kp8 + tg    ];
            ah[1] = Ph[(wm + gg + 8) * 36 + kp8 + tg    ];
            ah[2] = Ph[(wm + gg    ) * 36 + kp8 + tg + 4];
            ah[3] = Ph[(wm + gg + 8) * 36 + kp8 + tg + 4];
            al[0] = Pl[(wm + gg    ) * 36 + kp8 + tg    ];
            al[1] = Pl[(wm + gg + 8) * 36 + kp8 + tg    ];
            al[2] = Pl[(wm + gg    ) * 36 + kp8 + tg + 4];
            al[3] = Pl[(wm + gg + 8) * 36 + kp8 + tg + 4];
#pragma unroll
            for (int nt = 0; nt < 16; nt++) {
                int cn = nt * 8 + gg;
                unsigned bh0 = Vh[(kp8 + tg    ) * 132 + cn];
                unsigned bh1 = Vh[(kp8 + tg + 4) * 132 + cn];
                unsigned bl0 = Vl[(kp8 + tg    ) * 132 + cn];
                unsigned bl1 = Vl[(kp8 + tg + 4) * 132 + cn];
                MMA_BF16(c2[nt], ah, bh0, bh1);
                MMA_BF16(c2[nt], al, bh0, bh1);
                MMA_BF16(c2[nt], ah, bl0, bl1);
            }
        }
    }
    __syncthreads();

    // epilogue: write packed pairs directly (pair = h*64 + nt*4 + tg)
    {
        float inv0 = 1.f / rowl[wm + gg];
        float inv1 = 1.f / rowl[wm + gg + 8];
        int row0 = qt * 128 + wm + gg;
#pragma unroll
        for (int nt = 0; nt < 16; nt++) {
            int pair = h * 64 + nt * 4 + tg;
            unsigned hh, ll;
            split2(c2[nt][0] * inv0, c2[nt][1] * inv0, hh, ll);
            yph[((size_t)b * T_ + row0) * 1024 + pair] = hh;
            ypl[((size_t)b * T_ + row0) * 1024 + pair] = ll;
            split2(c2[nt][2] * inv1, c2[nt][3] * inv1, hh, ll);
            yph[((size_t)b * T_ + row0 + 8) * 1024 + pair] = hh;
            ypl[((size_t)b * T_ + row0 + 8) * 1024 + pair] = ll;
        }
    }
}

// ---------------- launch ----------------
extern "C" void kernel_launch(void* const* d_in, const int* in_sizes, int n_in,
                              void* d_out, int out_size) {
    const float* x    = (const float*)d_in[0];
    const float* cosp = (const float*)d_in[1];
    const float* sinp = (const float*)d_in[2];
    const float* Wq   = (const float*)d_in[3];
    const float* bq   = (const float*)d_in[4];
    const float* Wk   = (const float*)d_in[5];
    const float* bk   = (const float*)d_in[6];
    const float* Wv   = (const float*)d_in[7];
    const float* bv   = (const float*)d_in[8];
    const float* Wo   = (const float*)d_in[9];
    float* out = (float*)d_out;

    float *qt, *ktp, *vtp;
    cudaGetSymbolAddress((void**)&qt,  g_qt);
    cudaGetSymbolAddress((void**)&ktp, g_kt);
    cudaGetSymbolAddress((void**)&vtp, g_vt);
    unsigned *xph,*xpl,*yph,*ypl,*wqph,*wqpl,*wkph,*wkpl,*wvph,*wvpl,*woph,*wopl;
    unsigned *qph,*qpl,*kph,*kpl,*vph,*vpl;
    cudaGetSymbolAddress((void**)&xph, g_xph);   cudaGetSymbolAddress((void**)&xpl, g_xpl);
    cudaGetSymbolAddress((void**)&yph, g_yph);   cudaGetSymbolAddress((void**)&ypl, g_ypl);
    cudaGetSymbolAddress((void**)&wqph, g_wqph); cudaGetSymbolAddress((void**)&wqpl, g_wqpl);
    cudaGetSymbolAddress((void**)&wkph, g_wkph); cudaGetSymbolAddress((void**)&wkpl, g_wkpl);
    cudaGetSymbolAddress((void**)&wvph, g_wvph); cudaGetSymbolAddress((void**)&wvpl, g_wvpl);
    cudaGetSymbolAddress((void**)&woph, g_woph); cudaGetSymbolAddress((void**)&wopl, g_wopl);
    cudaGetSymbolAddress((void**)&qph, g_qph);   cudaGetSymbolAddress((void**)&qpl, g_qpl);
    cudaGetSymbolAddress((void**)&kph, g_kph);   cudaGetSymbolAddress((void**)&kpl, g_kpl);
    cudaGetSymbolAddress((void**)&vph, g_vph);   cudaGetSymbolAddress((void**)&vpl, g_vpl);

    // prep
    {
        int n8 = BT_ * C_ / 8;
        split_pack_rows<<<(n8 + 255)/256, 256>>>(x, xph, xpl, n8);
        int nwq = 1024 * 512;
        pack_w<<<(nwq + 255)/256, 256>>>(Wq, wqph, wqpl, C_, 2048);
        int nwk = 1024 * 128;
        pack_w<<<(nwk + 255)/256, 256>>>(Wk, wkph, wkpl, C_, 512);
        pack_w<<<(nwk + 255)/256, 256>>>(Wv, wvph, wvpl, C_, 512);
        pack_w<<<(nwq + 255)/256, 256>>>(Wo, woph, wopl, C_, 2048);
    }

    cudaFuncSetAttribute(gemm_pk_kernel, cudaFuncAttributeMaxDynamicSharedMemorySize, GB_BYTES);

    // QKV projections
    gemm_pk_kernel<<<dim3(16, 32), 256, GB_BYTES>>>(xph, xpl, wqph, wqpl, bq, qt,  BT_, 2048, 1024);
    gemm_pk_kernel<<<dim3(4,  32), 256, GB_BYTES>>>(xph, xpl, wkph, wkpl, bk, ktp, BT_, 512,  1024);
    gemm_pk_kernel<<<dim3(4,  32), 256, GB_BYTES>>>(xph, xpl, wvph, wvpl, bv, vtp, BT_, 512,  1024);

    // RoPE + pack
    {
        int nq = B_ * T_ * H_ * 32;
        rope_pack_kernel<<<(nq + 255)/256, 256>>>(qt, cosp, sinp, qph, qpl, H_);
        int nk = B_ * T_ * HK_ * 32;
        rope_pack_kt_kernel<<<(nk + 255)/256, 256>>>(ktp, cosp, sinp, kph, kpl);
        int nv = B_ * HK_ * (T_/2) * 32;
        pack_v_kernel<<<(nv + 255)/256, 256>>>(vtp, vph, vpl);
    }

    // attention (writes packed y directly)
    cudaFuncSetAttribute(attn_pk_kernel, cudaFuncAttributeMaxDynamicSharedMemorySize, AT_BYTES);
    attn_pk_kernel<<<dim3(T_/128, H_, B_), 256, AT_BYTES>>>(qph, qpl, kph, kpl, vph, vpl, yph, ypl);

    // out projection
    gemm_pk_kernel<<<dim3(16, 32), 256, GB_BYTES>>>(yph, ypl, woph, wopl, nullptr, out, BT_, C_, 1024);
}